// round 1
// baseline (speedup 1.0000x reference)
#include <cuda_runtime.h>

// Problem constants (fixed by setup_inputs)
#define NS      51      // hidden size
#define NSP     52      // padded hidden (units and K padded to even)
#define KP      26      // k-pairs (52/2)
#define TSEQ    2048
#define BATCH   8192
#define MROWS   64      // batch rows per CTA
#define NTHREADS 256
#define HSTRIDE 54      // h-row stride in floats (conflict-free LDS.64 across lanes)
#define CHUNK   32      // x/y staging chunk (timesteps)
#define XSTRIDE 33      // padded chunk stride

struct Smem {
    ulonglong2 W1[NSP * KP * 2];  // W_hh1 packed: [u][kp][{i,f},{g,o}] as f32x2 pairs
    ulonglong2 W2[NSP * KP * 2];  // W_ih2 packed
    ulonglong2 W3[NSP * KP * 2];  // W_hh2 packed
    float4 B1v[NSP];              // layer1 bias per gate (b_ih1+b_hh1)
    float4 XWv[NSP];              // W_ih1 per gate (input dim = 1)
    float4 B2v[NSP];              // layer2 bias per gate
    float  WL[NSP];               // W_lin
    float  H1[MROWS * HSTRIDE];
    float  H2[MROWS * HSTRIDE];
    float  XS[MROWS * XSTRIDE];
    float  YS[MROWS * XSTRIDE];
};

__device__ __forceinline__ unsigned long long ffma2(unsigned long long a,
                                                    unsigned long long b,
                                                    unsigned long long c) {
    unsigned long long d;
    asm("fma.rn.f32x2 %0, %1, %2, %3;" : "=l"(d) : "l"(a), "l"(b), "l"(c));
    return d;
}
__device__ __forceinline__ unsigned long long pack2(float lo, float hi) {
    unsigned long long r;
    asm("mov.b64 %0, {%1, %2};" : "=l"(r) : "f"(lo), "f"(hi));
    return r;
}
__device__ __forceinline__ float hsum2(unsigned long long a) {
    float lo, hi;
    asm("mov.b64 {%0, %1}, %2;" : "=f"(lo), "=f"(hi) : "l"(a));
    return lo + hi;
}
__device__ __forceinline__ float fsigmoid(float x) {
    float e;
    asm("ex2.approx.ftz.f32 %0, %1;" : "=f"(e) : "f"(-1.4426950408889634f * x));
    float r;
    asm("rcp.approx.ftz.f32 %0, %1;" : "=f"(r) : "f"(1.0f + e));
    return r;
}
__device__ __forceinline__ float ftanh(float x) {
    return fmaf(2.0f, fsigmoid(2.0f * x), -1.0f);
}

// Pack a [4*NS, NS] weight matrix into SMEM f32x2-pair layout.
// dst[(u*KP + kp)*2 + half] = float4{ Wg0[u][2kp], Wg0[u][2kp+1], Wg1[u][2kp], Wg1[u][2kp+1] }
// where (g0,g1) = (i,f) for half=0 and (g,o) for half=1. Pads (u>=NS, k>=NS) are zero.
__device__ void fill_w(ulonglong2* dst, const float* __restrict__ W, int tid) {
    for (int idx = tid; idx < NSP * KP * 2; idx += NTHREADS) {
        int u    = idx / (KP * 2);
        int rem  = idx - u * (KP * 2);
        int kp   = rem >> 1;
        int half = rem & 1;
        int g0 = half * 2, g1 = g0 + 1;
        int k0 = kp * 2,   k1 = k0 + 1;
        float4 v = make_float4(0.f, 0.f, 0.f, 0.f);
        if (u < NS) {
            const float* r0 = W + (g0 * NS + u) * NS;
            const float* r1 = W + (g1 * NS + u) * NS;
            v.x = r0[k0];                         // k0 <= 50 always valid
            v.y = (k1 < NS) ? r0[k1] : 0.f;
            v.z = r1[k0];
            v.w = (k1 < NS) ? r1[k1] : 0.f;
        }
        reinterpret_cast<float4*>(dst)[idx] = v;
    }
}

__global__ __launch_bounds__(NTHREADS, 1)
void lstm2_seq_kernel(const float* __restrict__ x,
                      const float* __restrict__ Wih1, const float* __restrict__ Whh1,
                      const float* __restrict__ bih1, const float* __restrict__ bhh1,
                      const float* __restrict__ Wih2, const float* __restrict__ Whh2,
                      const float* __restrict__ bih2, const float* __restrict__ bhh2,
                      const float* __restrict__ Wlin, const float* __restrict__ blin,
                      float* __restrict__ out) {
    extern __shared__ char smraw[];
    Smem* s = reinterpret_cast<Smem*>(smraw);
    const int tid = threadIdx.x;

    // ---- one-time SMEM setup ----
    fill_w(s->W1, Whh1, tid);
    fill_w(s->W2, Wih2, tid);
    fill_w(s->W3, Whh2, tid);
    for (int u = tid; u < NSP; u += NTHREADS) {
        float4 b1 = make_float4(0.f, 0.f, 0.f, 0.f);
        float4 xw = b1, b2 = b1;
        float wl = 0.f;
        if (u < NS) {
            b1 = make_float4(bih1[u] + bhh1[u],
                             bih1[NS + u] + bhh1[NS + u],
                             bih1[2 * NS + u] + bhh1[2 * NS + u],
                             bih1[3 * NS + u] + bhh1[3 * NS + u]);
            xw = make_float4(Wih1[u], Wih1[NS + u], Wih1[2 * NS + u], Wih1[3 * NS + u]);
            b2 = make_float4(bih2[u] + bhh2[u],
                             bih2[NS + u] + bhh2[NS + u],
                             bih2[2 * NS + u] + bhh2[2 * NS + u],
                             bih2[3 * NS + u] + bhh2[3 * NS + u]);
            wl = Wlin[u];
        }
        s->B1v[u] = b1;
        s->XWv[u] = xw;
        s->B2v[u] = b2;
        s->WL[u]  = wl;
    }
    for (int i = tid; i < MROWS * HSTRIDE; i += NTHREADS) {
        s->H1[i] = 0.f;
        s->H2[i] = 0.f;
    }
    __syncthreads();

    // thread mapping: warp = 32 consecutive rows of one unit-group
    const int r  = tid & (MROWS - 1);   // row 0..63
    const int ug = tid >> 6;            // unit-group 0..3 (13 units each)
    const int u0 = ug * 13;
    const int rb = blockIdx.x * MROWS;
    const float bl = blin[0];

    float c1[13], c2[13];
#pragma unroll
    for (int i = 0; i < 13; i++) { c1[i] = 0.f; c2[i] = 0.f; }

    float* h1row = s->H1 + r * HSTRIDE;
    float* h2row = s->H2 + r * HSTRIDE;

    for (int t = 0; t < TSEQ; t++) {
        if ((t & (CHUNK - 1)) == 0) {
            __syncthreads();
            if (t) {
                const int t0 = t - CHUNK;
                for (int idx = tid; idx < MROWS * CHUNK; idx += NTHREADS) {
                    int row = idx >> 5, c = idx & 31;
                    out[(long long)(rb + row) * TSEQ + t0 + c] = s->YS[row * XSTRIDE + c];
                }
            }
            for (int idx = tid; idx < MROWS * CHUNK; idx += NTHREADS) {
                int row = idx >> 5, c = idx & 31;
                s->XS[row * XSTRIDE + c] = x[(long long)(rb + row) * TSEQ + t + c];
            }
            __syncthreads();
        }
        const float xt = s->XS[r * XSTRIDE + (t & (CHUNK - 1))];

        // ---- layer 1: gates1 = h1 @ W_hh1^T + x_t*W_ih1 + b1 ----
        float h1n[13];
#pragma unroll
        for (int uu = 0; uu < 13; uu++) {
            const int u = u0 + uu;
            const float4 bb = s->B1v[u];
            const float4 xw = s->XWv[u];
            unsigned long long ai = pack2(bb.x, xt * xw.x);
            unsigned long long af = pack2(bb.y, xt * xw.y);
            unsigned long long ag = pack2(bb.z, xt * xw.z);
            unsigned long long ao = pack2(bb.w, xt * xw.w);
            const ulonglong2* wp = s->W1 + u * (KP * 2);
#pragma unroll
            for (int kp = 0; kp < KP; kp++) {
                const unsigned long long hp =
                    *reinterpret_cast<const unsigned long long*>(h1row + 2 * kp);
                const ulonglong2 wA = wp[2 * kp];
                const ulonglong2 wB = wp[2 * kp + 1];
                ai = ffma2(wA.x, hp, ai);
                af = ffma2(wA.y, hp, af);
                ag = ffma2(wB.x, hp, ag);
                ao = ffma2(wB.y, hp, ao);
            }
            const float gi = fsigmoid(hsum2(ai));
            const float gf = fsigmoid(hsum2(af));
            const float gg = ftanh(hsum2(ag));
            const float go = fsigmoid(hsum2(ao));
            const float c = fmaf(gf, c1[uu], gi * gg);
            c1[uu] = c;
            h1n[uu] = go * ftanh(c);
        }
        __syncthreads();
#pragma unroll
        for (int uu = 0; uu < 13; uu++) h1row[u0 + uu] = h1n[uu];
        __syncthreads();

        // ---- layer 2: gates2 = h1_new @ W_ih2^T + h2 @ W_hh2^T + b2 ----
        float h2n[13];
#pragma unroll
        for (int uu = 0; uu < 13; uu++) {
            const int u = u0 + uu;
            const float4 bb = s->B2v[u];
            unsigned long long ai = pack2(bb.x, 0.f);
            unsigned long long af = pack2(bb.y, 0.f);
            unsigned long long ag = pack2(bb.z, 0.f);
            unsigned long long ao = pack2(bb.w, 0.f);
            const ulonglong2* wp2 = s->W2 + u * (KP * 2);
            const ulonglong2* wp3 = s->W3 + u * (KP * 2);
#pragma unroll
            for (int kp = 0; kp < KP; kp++) {
                const unsigned long long hp1 =
                    *reinterpret_cast<const unsigned long long*>(h1row + 2 * kp);
                const unsigned long long hp2 =
                    *reinterpret_cast<const unsigned long long*>(h2row + 2 * kp);
                ulonglong2 wA = wp2[2 * kp];
                ulonglong2 wB = wp2[2 * kp + 1];
                ai = ffma2(wA.x, hp1, ai);
                af = ffma2(wA.y, hp1, af);
                ag = ffma2(wB.x, hp1, ag);
                ao = ffma2(wB.y, hp1, ao);
                wA = wp3[2 * kp];
                wB = wp3[2 * kp + 1];
                ai = ffma2(wA.x, hp2, ai);
                af = ffma2(wA.y, hp2, af);
                ag = ffma2(wB.x, hp2, ag);
                ao = ffma2(wB.y, hp2, ao);
            }
            const float gi = fsigmoid(hsum2(ai));
            const float gf = fsigmoid(hsum2(af));
            const float gg = ftanh(hsum2(ag));
            const float go = fsigmoid(hsum2(ao));
            const float c = fmaf(gf, c2[uu], gi * gg);
            c2[uu] = c;
            h2n[uu] = go * ftanh(c);
        }
        __syncthreads();
#pragma unroll
        for (int uu = 0; uu < 13; uu++) h2row[u0 + uu] = h2n[uu];
        __syncthreads();

        // ---- projection: y = h2 . W_lin + b_lin (unit-group 0 threads) ----
        if (ug == 0) {
            float y = bl;
#pragma unroll
            for (int u = 0; u < NSP; u++) y = fmaf(h2row[u], s->WL[u], y);
            s->YS[r * XSTRIDE + (t & (CHUNK - 1))] = y;
        }
    }

    // final chunk flush
    __syncthreads();
    for (int idx = tid; idx < MROWS * CHUNK; idx += NTHREADS) {
        int row = idx >> 5, c = idx & 31;
        out[(long long)(rb + row) * TSEQ + (TSEQ - CHUNK) + c] = s->YS[row * XSTRIDE + c];
    }
}

extern "C" void kernel_launch(void* const* d_in, const int* in_sizes, int n_in,
                              void* d_out, int out_size) {
    const float* x    = (const float*)d_in[0];
    const float* Wih1 = (const float*)d_in[1];
    const float* Whh1 = (const float*)d_in[2];
    const float* bih1 = (const float*)d_in[3];
    const float* bhh1 = (const float*)d_in[4];
    const float* Wih2 = (const float*)d_in[5];
    const float* Whh2 = (const float*)d_in[6];
    const float* bih2 = (const float*)d_in[7];
    const float* bhh2 = (const float*)d_in[8];
    const float* Wlin = (const float*)d_in[9];
    const float* blin = (const float*)d_in[10];
    // d_in[11] = future (always 0) — unused

    cudaFuncSetAttribute(lstm2_seq_kernel,
                         cudaFuncAttributeMaxDynamicSharedMemorySize,
                         (int)sizeof(Smem));

    lstm2_seq_kernel<<<BATCH / MROWS, NTHREADS, sizeof(Smem)>>>(
        x, Wih1, Whh1, bih1, bhh1, Wih2, Whh2, bih2, bhh2, Wlin, blin,
        (float*)d_out);
}